// round 12
// baseline (speedup 1.0000x reference)
#include <cuda_runtime.h>

#define Tv 1000
#define Dv 1024
#define NCHUNK 125   // 125 chunks x 8 rows = 1000

// Scratch (__device__ globals per allocation rules)
__device__ float g_part[NCHUNK * 8 * 1024];  // per-chunk partial t-sums
__device__ float g_vsump[16 * 8 * 64];       // 16 j-slice partials of vsum

// Streaming (evict-first) 128-bit store: keep `out` from polluting L2.
static __device__ __forceinline__ void stcs128(float4* p, float4 v) {
    asm volatile("st.global.cs.v4.f32 [%0], {%1, %2, %3, %4};"
                 :: "l"(p), "f"(v.x), "f"(v.y), "f"(v.z), "f"(v.w) : "memory");
}

// ---------------------------------------------------------------------------
// 1) Partial sums over t: grid (125, 8), 256 threads, 8 batched LDG.128.
// ---------------------------------------------------------------------------
__global__ void __launch_bounds__(256)
xsum_part_kernel(const float* __restrict__ x)
{
    const int chunk = blockIdx.x;
    const int b     = blockIdx.y;
    const int j4    = threadIdx.x << 2;

    const float4* xp = (const float4*)(x + ((size_t)b * Tv + chunk * 8) * Dv + j4);
    float4 v0 = xp[0 * 256], v1 = xp[1 * 256], v2 = xp[2 * 256], v3 = xp[3 * 256];
    float4 v4 = xp[4 * 256], v5 = xp[5 * 256], v6 = xp[6 * 256], v7 = xp[7 * 256];

    float4 acc;
    acc.x = ((v0.x + v1.x) + (v2.x + v3.x)) + ((v4.x + v5.x) + (v6.x + v7.x));
    acc.y = ((v0.y + v1.y) + (v2.y + v3.y)) + ((v4.y + v5.y) + (v6.y + v7.y));
    acc.z = ((v0.z + v1.z) + (v2.z + v3.z)) + ((v4.z + v5.z) + (v6.z + v7.z));
    acc.w = ((v0.w + v1.w) + (v2.w + v3.w)) + ((v4.w + v5.w) + (v6.w + v7.w));

    *(float4*)(g_part + ((size_t)(chunk * 8 + b)) * Dv + j4) = acc;
}

// ---------------------------------------------------------------------------
// 2) vsum partials: grid (8 b, 16 jb). Each block owns a 64-wide j slice.
// ---------------------------------------------------------------------------
__global__ void __launch_bounds__(256)
vsum_part_kernel(const float* __restrict__ Wv)
{
    __shared__ float xr[4][64];
    __shared__ float xs[64];
    __shared__ float p[4][64];
    const int b   = blockIdx.x;
    const int jb  = blockIdx.y;
    const int tid = threadIdx.x;
    const int j   = tid & 63;
    const int seg = tid >> 6;
    const int jg  = jb * 64;

    {
        const int c0 = seg * 31;
        const int cn = (seg == 3) ? 32 : 31;
        float s = 0.f;
        #pragma unroll 31
        for (int c = 0; c < cn; c++)
            s += g_part[((size_t)((c0 + c) * 8 + b)) * Dv + jg + j];
        xr[seg][j] = s;
    }
    __syncthreads();
    if (seg == 0)
        xs[j] = xr[0][j] + xr[1][j] + xr[2][j] + xr[3][j];
    __syncthreads();

    {
        float acc = 0.f;
        #pragma unroll
        for (int jj = 0; jj < 16; jj++) {
            int jl = seg * 16 + jj;
            acc += xs[jl] * Wv[(size_t)(jg + jl) * 64 + j];
        }
        p[seg][j] = acc;
    }
    __syncthreads();
    if (seg == 0)
        g_vsump[(jb * 8 + b) * 64 + j] = p[0][j] + p[1][j] + p[2][j] + p[3][j];
}

// ---------------------------------------------------------------------------
// 3) Fused row-GEMV + broadcast. grid (16 col-slices, 8 t-chunks), 256 thr.
//    Block: assemble vs[8][64]; GEMV its 64-col slice for all 8 batches
//    (Wo slice from L2, folded (m, m+64) pairs); stream 8b x 125t x 64col
//    with .cs stores.
// ---------------------------------------------------------------------------
__global__ void __launch_bounds__(256)
row_bcast_kernel(const float* __restrict__ Wo, const float* __restrict__ bv,
                 const float* __restrict__ bo, float* __restrict__ out)
{
    __shared__ float vs[8 * 64];        // vsum[b][d]
    __shared__ float part[4][8][64];    // [seg][b][n]
    __shared__ __align__(16) float fin[8][64];  // final slice [b][n]

    const int cs  = blockIdx.x;         // 0..15 col-slice (64 cols)
    const int tc  = blockIdx.y;         // 0..7 t-chunk (125 rows)
    const int tid = threadIdx.x;
    const int n   = tid & 63;           // col within slice
    const int seg = tid >> 6;           // 0..3: m-range [seg*256, seg*256+256)
    const int gn  = cs * 64 + n;        // global col

    // Assemble vsum: 16 j-slice partials + T*bv. 512 outputs, 2 per thread.
    #pragma unroll
    for (int i = tid; i < 512; i += 256) {
        int d = i & 63;
        float s = (float)Tv * bv[d];
        #pragma unroll
        for (int jb = 0; jb < 16; jb++)
            s += g_vsump[jb * 512 + i];
        vs[i] = s;
    }
    __syncthreads();

    // GEMV: this seg covers m in [seg*256, seg*256+256) as 128 folded pairs.
    // Pair (m1, m1+64) shares d = m1 & 63.
    float acc[8] = {};
    #pragma unroll 2
    for (int g = 0; g < 2; g++) {
        const int mb = seg * 256 + g * 128;
        #pragma unroll 8
        for (int j = 0; j < 64; j++) {
            float w1 = Wo[(size_t)(mb + j) * Dv + gn];
            float w2 = Wo[(size_t)(mb + j + 64) * Dv + gn];
            float w  = w1 + w2;
            #pragma unroll
            for (int b = 0; b < 8; b++)
                acc[b] = fmaf(vs[b * 64 + j], w, acc[b]);
        }
    }
    #pragma unroll
    for (int b = 0; b < 8; b++)
        part[seg][b][n] = acc[b];
    __syncthreads();

    // Reduce 4 segs + bias -> fin. 512 outputs, 2 per thread.
    #pragma unroll
    for (int i = tid; i < 512; i += 256) {
        int nn = i & 63;
        fin[i >> 6][nn] = bo[cs * 64 + nn]
            + ((part[0][i >> 6][nn] + part[1][i >> 6][nn])
             + (part[2][i >> 6][nn] + part[3][i >> 6][nn]));
    }
    __syncthreads();

    // Broadcast store: warp w owns batch b=w. Lanes: c4 = lane&15 (16 float4
    // covering 64 cols), tofs = lane>>4 (2 t-rows per iteration).
    {
        const int b    = tid >> 5;         // warp id = batch
        const int lane = tid & 31;
        const int c4   = lane & 15;
        const int tofs = lane >> 4;
        const int t0   = tc * 125;

        float4 v = *(const float4*)(&fin[b][c4 << 2]);
        float4* obase = (float4*)(out + ((size_t)(b * Tv + t0)) * Dv + cs * 64) + c4;

        #pragma unroll 4
        for (int i = 0; i < 62; i++) {
            int t = i * 2 + tofs;
            stcs128(obase + (size_t)t * 256, v);
        }
        if (tofs == 0)   // row 124 (125 rows total)
            stcs128(obase + (size_t)124 * 256, v);
    }
}

// ---------------------------------------------------------------------------
extern "C" void kernel_launch(void* const* d_in, const int* in_sizes, int n_in,
                              void* d_out, int out_size)
{
    const float* x  = (const float*)d_in[0];
    const float* Wv = (const float*)d_in[5];
    const float* bv = (const float*)d_in[6];
    const float* Wo = (const float*)d_in[7];
    const float* bo = (const float*)d_in[8];
    float* out = (float*)d_out;

    xsum_part_kernel<<<dim3(NCHUNK, 8), 256>>>(x);
    vsum_part_kernel<<<dim3(8, 16), 256>>>(Wv);
    row_bcast_kernel<<<dim3(16, 8), 256>>>(Wo, bv, bo, out);
}